// round 1
// baseline (speedup 1.0000x reference)
#include <cuda_runtime.h>
#include <math.h>

#define F_IN   4096
#define F_OUT  2048
#define BATCH  2048
#define N_ITER 10
#define SECURE_MIN 1e-5f
#define EPS_NORM   1e-20f

// Scratch (allocation-free: __device__ globals)
__device__ float g_Wn  [(size_t)F_OUT * F_IN];
__device__ float g_WnT [(size_t)F_IN  * F_OUT];
__device__ float g_xn  [(size_t)BATCH * F_IN];
__device__ float g_recon[(size_t)BATCH * F_IN];

// ---------------------------------------------------------------------------
// block-wide sum reduction (blockDim.x == 256)
// ---------------------------------------------------------------------------
__device__ __forceinline__ float block_reduce_sum(float v) {
    __shared__ float warp_sums[8];
    const int lane = threadIdx.x & 31;
    const int w    = threadIdx.x >> 5;
#pragma unroll
    for (int o = 16; o > 0; o >>= 1) v += __shfl_xor_sync(0xffffffffu, v, o);
    if (lane == 0) warp_sums[w] = v;
    __syncthreads();
    if (w == 0) {
        v = (lane < 8) ? warp_sums[lane] : 0.0f;
#pragma unroll
        for (int o = 4; o > 0; o >>= 1) v += __shfl_xor_sync(0xffffffffu, v, o);
        if (lane == 0) warp_sums[0] = v;
    }
    __syncthreads();
    return warp_sums[0];
}

// ---------------------------------------------------------------------------
// Row L1 normalize: dst = clip?(max(src,1e-5)) / max(sum(|clipped|), 1e-20)
// one block per row; cols divisible by 4; blockDim = 256
// ---------------------------------------------------------------------------
template <bool CLIP>
__global__ void rownorm_kernel(const float* __restrict__ src,
                               float* __restrict__ dst, int cols) {
    const size_t base = (size_t)blockIdx.x * cols;
    const float4* s4 = (const float4*)(src + base);
    float4*       d4 = (float4*)(dst + base);
    const int n4 = cols >> 2;
    float sum = 0.0f;
    for (int i = threadIdx.x; i < n4; i += blockDim.x) {
        float4 v = s4[i];
        if (CLIP) {
            v.x = fmaxf(v.x, SECURE_MIN); v.y = fmaxf(v.y, SECURE_MIN);
            v.z = fmaxf(v.z, SECURE_MIN); v.w = fmaxf(v.w, SECURE_MIN);
        }
        sum += fabsf(v.x) + fabsf(v.y) + fabsf(v.z) + fabsf(v.w);
    }
    const float tot = block_reduce_sum(sum);
    const float inv = 1.0f / fmaxf(tot, EPS_NORM);
    for (int i = threadIdx.x; i < n4; i += blockDim.x) {
        float4 v = s4[i];
        if (CLIP) {
            v.x = fmaxf(v.x, SECURE_MIN); v.y = fmaxf(v.y, SECURE_MIN);
            v.z = fmaxf(v.z, SECURE_MIN); v.w = fmaxf(v.w, SECURE_MIN);
        }
        v.x *= inv; v.y *= inv; v.z *= inv; v.w *= inv;
        d4[i] = v;
    }
}

// ---------------------------------------------------------------------------
// ratio: recon holds clip(h@Wn, 1e-5). Reference computes
//   recon_n = recon / max(sum(recon), 1e-20);  ratio = xn / recon_n
// fold: ratio = xn * max(sum,1e-20) / recon   (in place over recon)
// ---------------------------------------------------------------------------
__global__ void ratio_kernel(float* __restrict__ recon,
                             const float* __restrict__ xn, int cols) {
    const size_t base = (size_t)blockIdx.x * cols;
    float4*       r4 = (float4*)(recon + base);
    const float4* x4 = (const float4*)(xn + base);
    const int n4 = cols >> 2;
    float sum = 0.0f;
    for (int i = threadIdx.x; i < n4; i += blockDim.x) {
        float4 v = r4[i];
        sum += v.x + v.y + v.z + v.w;
    }
    float s = block_reduce_sum(sum);
    s = fmaxf(s, EPS_NORM);
    for (int i = threadIdx.x; i < n4; i += blockDim.x) {
        float4 v = r4[i];
        float4 x = x4[i];
        v.x = x.x * s / v.x; v.y = x.y * s / v.y;
        v.z = x.z * s / v.z; v.w = x.w * s / v.w;
        r4[i] = v;
    }
}

// ---------------------------------------------------------------------------
// 32x32 tiled transpose: out[c*rows + r] = in[r*cols + c]
// block (32,8); rows,cols divisible by 32
// ---------------------------------------------------------------------------
__global__ void transpose_kernel(const float* __restrict__ in,
                                 float* __restrict__ out, int rows, int cols) {
    __shared__ float tile[32][33];
    const int c  = blockIdx.x * 32 + threadIdx.x;
    const int r0 = blockIdx.y * 32;
#pragma unroll
    for (int i = threadIdx.y; i < 32; i += 8)
        tile[i][threadIdx.x] = in[(size_t)(r0 + i) * cols + c];
    __syncthreads();
    const int rO = r0 + threadIdx.x;           // output minor index (orig row)
    const int c0 = blockIdx.x * 32;            // output row base (orig col)
#pragma unroll
    for (int i = threadIdx.y; i < 32; i += 8)
        out[(size_t)(c0 + i) * rows + rO] = tile[threadIdx.x][i];
}

__global__ void fill_kernel(float* __restrict__ p, float val, int n) {
    const int i = blockIdx.x * blockDim.x + threadIdx.x;
    if (i < n) p[i] = val;
}

// ---------------------------------------------------------------------------
// SGEMM: C[M,N] = A[M,K] @ B[K,N], both row-major (A k-contig, B n-contig)
// 128x128 block tile, BK=8, 8x8 per thread, 256 threads, register prefetch.
// EPI = 1 : C = max(acc, 1e-5)                      (recon)
// EPI = 2 : C = max(C_old * acc, 1e-5)              (h multiplicative update)
// M,N divisible by 128, K divisible by 8.
// ---------------------------------------------------------------------------
template <int EPI>
__global__ __launch_bounds__(256, 2)
void sgemm_kernel(const float* __restrict__ A, const float* __restrict__ B,
                  float* __restrict__ C, int M, int N, int K) {
    constexpr int BM = 128, BN = 128, BK = 8;
    __shared__ float As[BK][BM + 4];
    __shared__ float Bs[BK][BN];

    const int tid  = threadIdx.x;
    const int tx   = tid & 15;        // 0..15  (N direction)
    const int ty   = tid >> 4;        // 0..15  (M direction)
    const int arow = tid >> 1;        // 0..127
    const int acol = (tid & 1) << 2;  // 0 or 4
    const int brow = tid >> 5;        // 0..7
    const int bcol = (tid & 31) << 2; // 0..124

    const float* Ag = A + (size_t)(blockIdx.y * BM + arow) * K + acol;
    const float* Bg = B + (size_t)brow * N + blockIdx.x * BN + bcol;

    float acc[8][8];
#pragma unroll
    for (int i = 0; i < 8; i++)
#pragma unroll
        for (int j = 0; j < 8; j++) acc[i][j] = 0.0f;

    float4 av = *(const float4*)(Ag);
    float4 bv = *(const float4*)(Bg);

    for (int k0 = 0; k0 < K; k0 += BK) {
        As[acol + 0][arow] = av.x;
        As[acol + 1][arow] = av.y;
        As[acol + 2][arow] = av.z;
        As[acol + 3][arow] = av.w;
        *(float4*)&Bs[brow][bcol] = bv;
        __syncthreads();

        if (k0 + BK < K) {
            av = *(const float4*)(Ag + k0 + BK);
            bv = *(const float4*)(Bg + (size_t)(k0 + BK) * N);
        }

#pragma unroll
        for (int k = 0; k < BK; k++) {
            float ra[8], rb[8];
            *(float4*)&ra[0] = *(const float4*)&As[k][ty * 8];
            *(float4*)&ra[4] = *(const float4*)&As[k][ty * 8 + 4];
            *(float4*)&rb[0] = *(const float4*)&Bs[k][tx * 8];
            *(float4*)&rb[4] = *(const float4*)&Bs[k][tx * 8 + 4];
#pragma unroll
            for (int i = 0; i < 8; i++)
#pragma unroll
                for (int j = 0; j < 8; j++)
                    acc[i][j] = fmaf(ra[i], rb[j], acc[i][j]);
        }
        __syncthreads();
    }

    float* Cg = C + (size_t)(blockIdx.y * BM + ty * 8) * N + blockIdx.x * BN + tx * 8;
#pragma unroll
    for (int i = 0; i < 8; i++) {
#pragma unroll
        for (int j4 = 0; j4 < 8; j4 += 4) {
            float4 v = *(float4*)&acc[i][j4];
            if (EPI == 1) {
                v.x = fmaxf(v.x, SECURE_MIN); v.y = fmaxf(v.y, SECURE_MIN);
                v.z = fmaxf(v.z, SECURE_MIN); v.w = fmaxf(v.w, SECURE_MIN);
            } else { // EPI == 2
                float4 h = *(const float4*)(Cg + (size_t)i * N + j4);
                v.x = fmaxf(h.x * v.x, SECURE_MIN);
                v.y = fmaxf(h.y * v.y, SECURE_MIN);
                v.z = fmaxf(h.z * v.z, SECURE_MIN);
                v.w = fmaxf(h.w * v.w, SECURE_MIN);
            }
            *(float4*)(Cg + (size_t)i * N + j4) = v;
        }
    }
}

// ---------------------------------------------------------------------------
extern "C" void kernel_launch(void* const* d_in, const int* in_sizes, int n_in,
                              void* d_out, int out_size) {
    const float* x = (const float*)d_in[0];  // (BATCH, F_IN)
    const float* W = (const float*)d_in[1];  // (F_OUT, F_IN)
    float* h = (float*)d_out;                // (BATCH, F_OUT)

    float *Wn, *WnT, *xn, *recon;
    cudaGetSymbolAddress((void**)&Wn,    g_Wn);
    cudaGetSymbolAddress((void**)&WnT,   g_WnT);
    cudaGetSymbolAddress((void**)&xn,    g_xn);
    cudaGetSymbolAddress((void**)&recon, g_recon);

    // Prep: Wn = l1norm(clip(W)), WnT = Wn^T, xn = l1norm(x), h0 = 1/F_OUT
    rownorm_kernel<true ><<<F_OUT, 256>>>(W, Wn, F_IN);
    rownorm_kernel<false><<<BATCH, 256>>>(x, xn, F_IN);
    transpose_kernel<<<dim3(F_IN / 32, F_OUT / 32), dim3(32, 8)>>>(Wn, WnT, F_OUT, F_IN);
    {
        const int n = BATCH * F_OUT;
        fill_kernel<<<(n + 255) / 256, 256>>>(h, 1.0f / (float)F_OUT, n);
    }

    for (int it = 0; it < N_ITER; ++it) {
        // recon = clip(h @ Wn, 1e-5)                     (BATCH x F_IN)
        sgemm_kernel<1><<<dim3(F_IN / 128, BATCH / 128), 256>>>(
            h, Wn, recon, BATCH, F_IN, F_OUT);
        // recon <- xn * rowsum(recon) / recon  (== xn / l1norm(recon))
        ratio_kernel<<<BATCH, 256>>>(recon, xn, F_IN);
        // h = clip(h * (recon @ Wn^T), 1e-5)             (BATCH x F_OUT)
        sgemm_kernel<2><<<dim3(F_OUT / 128, BATCH / 128), 256>>>(
            recon, WnT, h, BATCH, F_OUT, F_IN);
        // h = l1norm(h)
        rownorm_kernel<false><<<BATCH, 256>>>(h, h, F_OUT);
    }
}

// round 3
// speedup vs baseline: 3.9495x; 3.9495x over previous
#include <cuda_runtime.h>
#include <math.h>
#include <stdint.h>

#define F_IN   4096
#define F_OUT  2048
#define BATCH  2048
#define N_ITER 10
#define SECURE_MIN 1e-5f
#define EPS_NORM   1e-20f

// ---------------- GEMM tiling ----------------
#define BM 128
#define BN 128
#define BK 32                       // 32 tf32 = 128 B per row
#define STAGES 3
#define TILE_BYTES (BM * BK * 4)    // 16 KB each for A and B
#define STAGE_BYTES (2 * TILE_BYTES)
#define SMEM_TOTAL (STAGES * STAGE_BYTES)  // 96 KB

// ---------------- scratch (__device__ globals; no allocs) ----------------
__device__ __align__(1024) float g_Wn   [(size_t)F_OUT * F_IN];
__device__ __align__(1024) float g_WnT  [(size_t)F_IN  * F_OUT];
__device__ __align__(1024) float g_xn   [(size_t)BATCH * F_IN];
__device__ __align__(1024) float g_recon[(size_t)BATCH * F_IN];
__device__ __align__(1024) float g_ht   [(size_t)BATCH * F_OUT];

// ---------------- PTX helpers (portable sm_80+) ----------------
__device__ __forceinline__ uint32_t smem_u32(const void* p) {
    uint32_t a;
    asm("{ .reg .u64 t; cvta.to.shared.u64 t, %1; cvt.u32.u64 %0, t; }"
        : "=r"(a) : "l"(p));
    return a;
}
__device__ __forceinline__ float to_tf32(float x) {
    float r;
    asm("cvt.rna.tf32.f32 %0, %1;" : "=f"(r) : "f"(x));
    return r;
}
__device__ __forceinline__ void cp_async16(uint32_t dst, const void* src) {
    asm volatile("cp.async.cg.shared.global [%0], [%1], 16;"
                 :: "r"(dst), "l"(src) : "memory");
}
__device__ __forceinline__ void cp_commit() {
    asm volatile("cp.async.commit_group;" ::: "memory");
}
template <int N>
__device__ __forceinline__ void cp_wait() {
    asm volatile("cp.async.wait_group %0;" :: "n"(N) : "memory");
}
__device__ __forceinline__ void ldm_x4(uint32_t& r0, uint32_t& r1,
                                       uint32_t& r2, uint32_t& r3, uint32_t a) {
    asm volatile("ldmatrix.sync.aligned.m8n8.x4.shared.b16 {%0,%1,%2,%3}, [%4];"
                 : "=r"(r0), "=r"(r1), "=r"(r2), "=r"(r3) : "r"(a));
}
__device__ __forceinline__ void mma_tf32(float* d, const uint32_t* a,
                                         const uint32_t* b) {
    asm volatile(
        "mma.sync.aligned.m16n8k8.row.col.f32.tf32.tf32.f32 "
        "{%0,%1,%2,%3}, {%4,%5,%6,%7}, {%8,%9}, {%0,%1,%2,%3};"
        : "+f"(d[0]), "+f"(d[1]), "+f"(d[2]), "+f"(d[3])
        : "r"(a[0]), "r"(a[1]), "r"(a[2]), "r"(a[3]), "r"(b[0]), "r"(b[1]));
}

// ---------------- tf32 mma.sync GEMM ----------------
// C[M,N] = A[M,K] @ B_rows[N,K]^T  (A K-contig ld=K, B K-contig ld=K)
// EPI=1: C = max(acc, 1e-5)     EPI=2: C = max(C_old * acc, 1e-5)
template <int EPI>
__global__ void __launch_bounds__(256)
gemm_tf32(const float* __restrict__ A, const float* __restrict__ B,
          float* __restrict__ C, int K, int Nglob) {
    extern __shared__ char smem[];
    const uint32_t sb = smem_u32(smem);

    const int tid  = threadIdx.x;
    const int warp = tid >> 5;
    const int lane = tid & 31;
    const int m0 = blockIdx.y * BM;
    const int n0 = blockIdx.x * BN;
    const int wm = (warp >> 1) << 5;   // 0,32,64,96
    const int wn = (warp & 1) << 6;    // 0,64

    // cp.async per-thread mapping: 1024 16B-chunks per tile, 4 per thread
    const int crow = tid >> 3;         // base row (0..31 step: +32 per q)
    const int cch  = tid & 7;          // 16B chunk within 128B row

    // ldmatrix per-lane fragment addressing (XOR-swizzled)
    const int rowA = wm + (lane & 15);
    const int selA = lane >> 4;                 // +0/+1 chunk pair
    const int rowB0 = wn + (lane & 7) + ((lane & 16) ? 8 : 0);
    const int selB = (lane >> 3) & 1;

    float acc[2][8][4];
#pragma unroll
    for (int i = 0; i < 2; i++)
#pragma unroll
        for (int j = 0; j < 8; j++)
#pragma unroll
            for (int k = 0; k < 4; k++) acc[i][j][k] = 0.0f;

    const int nkt = K / BK;

    auto load_stage = [&](int kt, int st) {
        const uint32_t sA = sb + st * STAGE_BYTES;
        const uint32_t sB = sA + TILE_BYTES;
        const float* gA = A + (size_t)m0 * K + kt * BK;
        const float* gB = B + (size_t)n0 * K + kt * BK;
#pragma unroll
        for (int q = 0; q < 4; q++) {
            const int r = crow + q * 32;
            const uint32_t soff = r * 128 + ((cch ^ (r & 7)) << 4);
            cp_async16(sA + soff, gA + (size_t)r * K + cch * 4);
            cp_async16(sB + soff, gB + (size_t)r * K + cch * 4);
        }
        cp_commit();
    };

    // prologue
    load_stage(0, 0);
    if (nkt > 1) load_stage(1, 1); else cp_commit();

    for (int kt = 0; kt < nkt; kt++) {
        cp_wait<1>();
        __syncthreads();
        if (kt + 2 < nkt) load_stage(kt + 2, (kt + 2) % STAGES);
        else cp_commit();

        const uint32_t sA = sb + (kt % STAGES) * STAGE_BYTES;
        const uint32_t sB = sA + TILE_BYTES;
#pragma unroll
        for (int ks = 0; ks < BK / 8; ks++) {
            uint32_t a[2][4], b[4][4];
#pragma unroll
            for (int mi = 0; mi < 2; mi++) {
                const int r = rowA + mi * 16;
                const uint32_t ad = sA + r * 128 +
                                    (((ks * 2 + selA) ^ (r & 7)) << 4);
                ldm_x4(a[mi][0], a[mi][1], a[mi][2], a[mi][3], ad);
            }
#pragma unroll
            for (int g = 0; g < 4; g++) {
                const int r = rowB0 + g * 16;
                const uint32_t bd = sB + r * 128 +
                                    (((ks * 2 + selB) ^ (r & 7)) << 4);
                ldm_x4(b[g][0], b[g][1], b[g][2], b[g][3], bd);
            }
#pragma unroll
            for (int mi = 0; mi < 2; mi++)
#pragma unroll
                for (int g = 0; g < 4; g++) {
                    mma_tf32(acc[mi][2 * g + 0], a[mi], &b[g][0]);
                    mma_tf32(acc[mi][2 * g + 1], a[mi], &b[g][2]);
                }
        }
        __syncthreads();
    }

    // epilogue: c0,c1 at (row, col..col+1), c2,c3 at (row+8, ..)
    const int erow = m0 + wm + (lane >> 2);
    const int ecol = n0 + wn + (lane & 3) * 2;
#pragma unroll
    for (int mi = 0; mi < 2; mi++) {
#pragma unroll
        for (int ni = 0; ni < 8; ni++) {
#pragma unroll
            for (int half = 0; half < 2; half++) {
                const int r = erow + mi * 16 + half * 8;
                float* p = C + (size_t)r * Nglob + ecol + ni * 8;
                float2 v;
                v.x = acc[mi][ni][2 * half + 0];
                v.y = acc[mi][ni][2 * half + 1];
                if (EPI == 1) {
                    v.x = fmaxf(v.x, SECURE_MIN);
                    v.y = fmaxf(v.y, SECURE_MIN);
                } else {
                    float2 h = *(const float2*)p;
                    v.x = fmaxf(h.x * v.x, SECURE_MIN);
                    v.y = fmaxf(h.y * v.y, SECURE_MIN);
                }
                *(float2*)p = v;
            }
        }
    }
}

// ---------------- elementwise ----------------
__device__ __forceinline__ float block_reduce_sum(float v) {
    __shared__ float ws[8];
    const int lane = threadIdx.x & 31;
    const int w    = threadIdx.x >> 5;
#pragma unroll
    for (int o = 16; o > 0; o >>= 1) v += __shfl_xor_sync(0xffffffffu, v, o);
    if (lane == 0) ws[w] = v;
    __syncthreads();
    if (w == 0) {
        v = (lane < 8) ? ws[lane] : 0.0f;
#pragma unroll
        for (int o = 4; o > 0; o >>= 1) v += __shfl_xor_sync(0xffffffffu, v, o);
        if (lane == 0) ws[0] = v;
    }
    __syncthreads();
    return ws[0];
}

// MODE 0: dst = l1norm(src)                        (xn; fp32)
// MODE 1: dst = tf32(l1norm(max(src,1e-5)))        (Wn prep)
// MODE 2: dst = l1norm(src) fp32; dst2 = tf32 copy (h + h_t)
template <int MODE>
__global__ void rownorm_kernel(const float* __restrict__ src,
                               float* __restrict__ dst,
                               float* __restrict__ dst2, int cols) {
    const size_t base = (size_t)blockIdx.x * cols;
    const float4* s4 = (const float4*)(src + base);
    float4* d4  = (float4*)(dst + base);
    float4* d24 = (MODE == 2) ? (float4*)(dst2 + base) : nullptr;
    const int n4 = cols >> 2;
    float sum = 0.0f;
    for (int i = threadIdx.x; i < n4; i += blockDim.x) {
        float4 v = s4[i];
        if (MODE == 1) {
            v.x = fmaxf(v.x, SECURE_MIN); v.y = fmaxf(v.y, SECURE_MIN);
            v.z = fmaxf(v.z, SECURE_MIN); v.w = fmaxf(v.w, SECURE_MIN);
        }
        sum += fabsf(v.x) + fabsf(v.y) + fabsf(v.z) + fabsf(v.w);
    }
    const float tot = block_reduce_sum(sum);
    const float inv = 1.0f / fmaxf(tot, EPS_NORM);
    for (int i = threadIdx.x; i < n4; i += blockDim.x) {
        float4 v = s4[i];
        if (MODE == 1) {
            v.x = fmaxf(v.x, SECURE_MIN); v.y = fmaxf(v.y, SECURE_MIN);
            v.z = fmaxf(v.z, SECURE_MIN); v.w = fmaxf(v.w, SECURE_MIN);
        }
        v.x *= inv; v.y *= inv; v.z *= inv; v.w *= inv;
        if (MODE == 1) {
            v.x = to_tf32(v.x); v.y = to_tf32(v.y);
            v.z = to_tf32(v.z); v.w = to_tf32(v.w);
        }
        d4[i] = v;
        if (MODE == 2) {
            float4 t;
            t.x = to_tf32(v.x); t.y = to_tf32(v.y);
            t.z = to_tf32(v.z); t.w = to_tf32(v.w);
            d24[i] = t;
        }
    }
}

// recon holds clip(h@Wn,1e-5). In place: ratio = tf32(xn * max(rowsum,eps)/recon)
__global__ void ratio_kernel(float* __restrict__ recon,
                             const float* __restrict__ xn, int cols) {
    const size_t base = (size_t)blockIdx.x * cols;
    float4*       r4 = (float4*)(recon + base);
    const float4* x4 = (const float4*)(xn + base);
    const int n4 = cols >> 2;
    float sum = 0.0f;
    for (int i = threadIdx.x; i < n4; i += blockDim.x) {
        float4 v = r4[i];
        sum += v.x + v.y + v.z + v.w;
    }
    float s = block_reduce_sum(sum);
    s = fmaxf(s, EPS_NORM);
    for (int i = threadIdx.x; i < n4; i += blockDim.x) {
        float4 v = r4[i];
        float4 x = x4[i];
        v.x = to_tf32(x.x * s / v.x); v.y = to_tf32(x.y * s / v.y);
        v.z = to_tf32(x.z * s / v.z); v.w = to_tf32(x.w * s / v.w);
        r4[i] = v;
    }
}

__global__ void transpose_kernel(const float* __restrict__ in,
                                 float* __restrict__ out, int rows, int cols) {
    __shared__ float tile[32][33];
    const int c  = blockIdx.x * 32 + threadIdx.x;
    const int r0 = blockIdx.y * 32;
#pragma unroll
    for (int i = threadIdx.y; i < 32; i += 8)
        tile[i][threadIdx.x] = in[(size_t)(r0 + i) * cols + c];
    __syncthreads();
    const int rO = r0 + threadIdx.x;
    const int c0 = blockIdx.x * 32;
#pragma unroll
    for (int i = threadIdx.y; i < 32; i += 8)
        out[(size_t)(c0 + i) * rows + rO] = tile[threadIdx.x][i];
}

__global__ void fill_kernel(float* __restrict__ a, float* __restrict__ b,
                            float val, int n) {
    const int i = blockIdx.x * blockDim.x + threadIdx.x;
    if (i < n) { a[i] = val; b[i] = val; }
}

// ---------------- host ----------------
extern "C" void kernel_launch(void* const* d_in, const int* in_sizes, int n_in,
                              void* d_out, int out_size) {
    const float* x = (const float*)d_in[0];  // (BATCH, F_IN)
    const float* W = (const float*)d_in[1];  // (F_OUT, F_IN)
    float* h = (float*)d_out;                // (BATCH, F_OUT)

    float *Wn, *WnT, *xn, *recon, *ht;
    cudaGetSymbolAddress((void**)&Wn,    g_Wn);
    cudaGetSymbolAddress((void**)&WnT,   g_WnT);
    cudaGetSymbolAddress((void**)&xn,    g_xn);
    cudaGetSymbolAddress((void**)&recon, g_recon);
    cudaGetSymbolAddress((void**)&ht,    g_ht);

    cudaFuncSetAttribute(gemm_tf32<1>, cudaFuncAttributeMaxDynamicSharedMemorySize, SMEM_TOTAL);
    cudaFuncSetAttribute(gemm_tf32<2>, cudaFuncAttributeMaxDynamicSharedMemorySize, SMEM_TOTAL);

    // prep: Wn = tf32(l1norm(clip(W))), WnT = Wn^T, xn = l1norm(x), h0 = ht0 = 1/F_OUT
    rownorm_kernel<1><<<F_OUT, 256>>>(W, Wn, nullptr, F_IN);
    rownorm_kernel<0><<<BATCH, 256>>>(x, xn, nullptr, F_IN);
    transpose_kernel<<<dim3(F_IN / 32, F_OUT / 32), dim3(32, 8)>>>(Wn, WnT, F_OUT, F_IN);
    fill_kernel<<<(BATCH * F_OUT + 255) / 256, 256>>>(h, ht, 1.0f / (float)F_OUT,
                                                      BATCH * F_OUT);

    for (int it = 0; it < N_ITER; ++it) {
        // recon[B, F_IN] = ht[B, F_OUT] @ Wn : A=ht (K=F_OUT), Brows=WnT [F_IN, F_OUT]
        gemm_tf32<1><<<dim3(F_IN / BN, BATCH / BM), 256, SMEM_TOTAL>>>(
            ht, WnT, recon, F_OUT, F_IN);
        ratio_kernel<<<BATCH, 256>>>(recon, xn, F_IN);
        // h[B, F_OUT] = max(h * (ratio @ WnT), min) : A=ratio (K=F_IN), Brows=Wn
        gemm_tf32<2><<<dim3(F_OUT / BN, BATCH / BM), 256, SMEM_TOTAL>>>(
            recon, Wn, h, F_IN, F_OUT);
        rownorm_kernel<2><<<BATCH, 256>>>(h, h, ht, F_OUT);
    }
}

// round 4
// speedup vs baseline: 6.9944x; 1.7710x over previous
#include <cuda_runtime.h>
#include <cuda_fp16.h>
#include <math.h>
#include <stdint.h>

#define F_IN   4096
#define F_OUT  2048
#define BATCH  2048
#define N_ITER 10
#define SECURE_MIN 1e-5f
#define EPS_NORM   1e-20f

// static power-of-2 operand scales (exact; cancelled in epilogue)
#define S_W 65536.0f   // Wn, WnT
#define S_H 4096.0f    // ht
#define S_R 256.0f     // ratio
#define ESC1 (1.0f / (S_H * S_W))   // 2^-28
#define ESC2 (1.0f / (S_R * S_W))   // 2^-24

// ---------------- GEMM tiling (half operands) ----------------
#define BM 128
#define BN 128
#define BK 64                        // 64 halves = 128 B per row
#define STAGES 3
#define TILE_BYTES (BM * 128)        // 16 KB each for A and B
#define STAGE_BYTES (2 * TILE_BYTES)
#define SMEM_TOTAL (STAGES * STAGE_BYTES)  // 96 KB

// ---------------- scratch (__device__ globals; no allocs) ----------------
__device__ __align__(1024) __half g_Wn_h  [(size_t)F_OUT * F_IN];
__device__ __align__(1024) __half g_WnT_h [(size_t)F_IN  * F_OUT];
__device__ __align__(1024) __half g_rat_h [(size_t)BATCH * F_IN];
__device__ __align__(1024) __half g_ht_h  [(size_t)BATCH * F_OUT];
__device__ __align__(1024) float  g_xn    [(size_t)BATCH * F_IN];
__device__ __align__(1024) float  g_recon [(size_t)BATCH * F_IN];

// ---------------- PTX helpers (portable sm_80+) ----------------
__device__ __forceinline__ uint32_t smem_u32(const void* p) {
    uint32_t a;
    asm("{ .reg .u64 t; cvta.to.shared.u64 t, %1; cvt.u32.u64 %0, t; }"
        : "=r"(a) : "l"(p));
    return a;
}
__device__ __forceinline__ void cp_async16(uint32_t dst, const void* src) {
    asm volatile("cp.async.cg.shared.global [%0], [%1], 16;"
                 :: "r"(dst), "l"(src) : "memory");
}
__device__ __forceinline__ void cp_commit() {
    asm volatile("cp.async.commit_group;" ::: "memory");
}
template <int N>
__device__ __forceinline__ void cp_wait() {
    asm volatile("cp.async.wait_group %0;" :: "n"(N) : "memory");
}
__device__ __forceinline__ void ldm_x4(uint32_t& r0, uint32_t& r1,
                                       uint32_t& r2, uint32_t& r3, uint32_t a) {
    asm volatile("ldmatrix.sync.aligned.m8n8.x4.shared.b16 {%0,%1,%2,%3}, [%4];"
                 : "=r"(r0), "=r"(r1), "=r"(r2), "=r"(r3) : "r"(a));
}
__device__ __forceinline__ void mma_f16(float* d, const uint32_t* a,
                                        const uint32_t* b) {
    asm volatile(
        "mma.sync.aligned.m16n8k16.row.col.f32.f16.f16.f32 "
        "{%0,%1,%2,%3}, {%4,%5,%6,%7}, {%8,%9}, {%0,%1,%2,%3};"
        : "+f"(d[0]), "+f"(d[1]), "+f"(d[2]), "+f"(d[3])
        : "r"(a[0]), "r"(a[1]), "r"(a[2]), "r"(a[3]), "r"(b[0]), "r"(b[1]));
}

// ---------------- fp16 mma.sync GEMM ----------------
// C[M,N] = scale * (A[M,K] @ B_rows[N,K]^T), A/B half, K-contig.
// EPI=1: C = max(acc*esc, 1e-5)     EPI=2: C = max(C_old * acc*esc, 1e-5)
template <int EPI>
__global__ void __launch_bounds__(256)
gemm_f16(const __half* __restrict__ A, const __half* __restrict__ B,
         float* __restrict__ C, int K, int Nglob, float esc) {
    extern __shared__ char smem[];
    const uint32_t sb = smem_u32(smem);

    const int tid  = threadIdx.x;
    const int warp = tid >> 5;
    const int lane = tid & 31;
    const int m0 = blockIdx.y * BM;
    const int n0 = blockIdx.x * BN;
    const int wm = (warp >> 1) << 5;   // 0,32,64,96
    const int wn = (warp & 1) << 6;    // 0,64

    // cp.async mapping: 1024 16B-chunks per tile, 4 per thread
    const int crow = tid >> 3;         // 0..31 (+32 per q)
    const int cch  = tid & 7;          // 16B chunk within 128B row

    // ldmatrix lane addressing (same swizzle as validated tf32 kernel)
    const int rowA = wm + (lane & 15);
    const int selA = lane >> 4;
    const int rowB0 = wn + (lane & 7) + ((lane & 16) ? 8 : 0);
    const int selB = (lane >> 3) & 1;

    float acc[2][8][4];
#pragma unroll
    for (int i = 0; i < 2; i++)
#pragma unroll
        for (int j = 0; j < 8; j++)
#pragma unroll
            for (int k = 0; k < 4; k++) acc[i][j][k] = 0.0f;

    const int nkt = K / BK;

    auto load_stage = [&](int kt, int st) {
        const uint32_t sA = sb + st * STAGE_BYTES;
        const uint32_t sB = sA + TILE_BYTES;
        const __half* gA = A + (size_t)m0 * K + kt * BK;
        const __half* gB = B + (size_t)n0 * K + kt * BK;
#pragma unroll
        for (int q = 0; q < 4; q++) {
            const int r = crow + q * 32;
            const uint32_t soff = r * 128 + ((cch ^ (r & 7)) << 4);
            cp_async16(sA + soff, gA + (size_t)r * K + cch * 8);
            cp_async16(sB + soff, gB + (size_t)r * K + cch * 8);
        }
        cp_commit();
    };

    load_stage(0, 0);
    if (nkt > 1) load_stage(1, 1); else cp_commit();

    for (int kt = 0; kt < nkt; kt++) {
        cp_wait<1>();
        __syncthreads();
        if (kt + 2 < nkt) load_stage(kt + 2, (kt + 2) % STAGES);
        else cp_commit();

        const uint32_t sA = sb + (kt % STAGES) * STAGE_BYTES;
        const uint32_t sB = sA + TILE_BYTES;
#pragma unroll
        for (int ks = 0; ks < BK / 16; ks++) {     // 4 k16 steps
            uint32_t a[2][4], b[4][4];
#pragma unroll
            for (int mi = 0; mi < 2; mi++) {
                const int r = rowA + mi * 16;
                const uint32_t ad = sA + r * 128 +
                                    (((ks * 2 + selA) ^ (r & 7)) << 4);
                ldm_x4(a[mi][0], a[mi][1], a[mi][2], a[mi][3], ad);
            }
#pragma unroll
            for (int g = 0; g < 4; g++) {
                const int r = rowB0 + g * 16;
                const uint32_t bd = sB + r * 128 +
                                    (((ks * 2 + selB) ^ (r & 7)) << 4);
                ldm_x4(b[g][0], b[g][1], b[g][2], b[g][3], bd);
            }
#pragma unroll
            for (int mi = 0; mi < 2; mi++)
#pragma unroll
                for (int g = 0; g < 4; g++) {
                    mma_f16(acc[mi][2 * g + 0], a[mi], &b[g][0]);
                    mma_f16(acc[mi][2 * g + 1], a[mi], &b[g][2]);
                }
        }
        __syncthreads();
    }

    const int erow = m0 + wm + (lane >> 2);
    const int ecol = n0 + wn + (lane & 3) * 2;
#pragma unroll
    for (int mi = 0; mi < 2; mi++) {
#pragma unroll
        for (int ni = 0; ni < 8; ni++) {
#pragma unroll
            for (int half_ = 0; half_ < 2; half_++) {
                const int r = erow + mi * 16 + half_ * 8;
                float* p = C + (size_t)r * Nglob + ecol + ni * 8;
                float2 v;
                v.x = acc[mi][ni][2 * half_ + 0] * esc;
                v.y = acc[mi][ni][2 * half_ + 1] * esc;
                if (EPI == 1) {
                    v.x = fmaxf(v.x, SECURE_MIN);
                    v.y = fmaxf(v.y, SECURE_MIN);
                } else {
                    float2 h = *(const float2*)p;
                    v.x = fmaxf(h.x * v.x, SECURE_MIN);
                    v.y = fmaxf(h.y * v.y, SECURE_MIN);
                }
                *(float2*)p = v;
            }
        }
    }
}

// ---------------- elementwise ----------------
__device__ __forceinline__ float block_reduce_sum(float v) {
    __shared__ float ws[8];
    const int lane = threadIdx.x & 31;
    const int w    = threadIdx.x >> 5;
#pragma unroll
    for (int o = 16; o > 0; o >>= 1) v += __shfl_xor_sync(0xffffffffu, v, o);
    if (lane == 0) ws[w] = v;
    __syncthreads();
    if (w == 0) {
        v = (lane < 8) ? ws[lane] : 0.0f;
#pragma unroll
        for (int o = 4; o > 0; o >>= 1) v += __shfl_xor_sync(0xffffffffu, v, o);
        if (lane == 0) ws[0] = v;
    }
    __syncthreads();
    return ws[0];
}

__device__ __forceinline__ void store_h4(__half* dst, size_t i4, float4 v,
                                         float scale) {
    half2* p = (half2*)(dst + i4 * 4);
    p[0] = __floats2half2_rn(v.x * scale, v.y * scale);
    p[1] = __floats2half2_rn(v.z * scale, v.w * scale);
}

// MODE 0: dst_f = l1norm(src)                            (xn)
// MODE 1: dst_h = half(S_W * l1norm(max(src,1e-5)))      (Wn prep)
// MODE 2: dst_f = l1norm(src); dst_h = half(S_H * same)  (h + ht)
template <int MODE>
__global__ void rownorm_kernel(const float* __restrict__ src,
                               float* __restrict__ dst_f,
                               __half* __restrict__ dst_h, int cols) {
    const size_t base = (size_t)blockIdx.x * cols;
    const float4* s4 = (const float4*)(src + base);
    const int n4 = cols >> 2;
    float sum = 0.0f;
    for (int i = threadIdx.x; i < n4; i += blockDim.x) {
        float4 v = s4[i];
        if (MODE == 1) {
            v.x = fmaxf(v.x, SECURE_MIN); v.y = fmaxf(v.y, SECURE_MIN);
            v.z = fmaxf(v.z, SECURE_MIN); v.w = fmaxf(v.w, SECURE_MIN);
        }
        sum += fabsf(v.x) + fabsf(v.y) + fabsf(v.z) + fabsf(v.w);
    }
    const float tot = block_reduce_sum(sum);
    const float inv = 1.0f / fmaxf(tot, EPS_NORM);
    for (int i = threadIdx.x; i < n4; i += blockDim.x) {
        float4 v = s4[i];
        if (MODE == 1) {
            v.x = fmaxf(v.x, SECURE_MIN); v.y = fmaxf(v.y, SECURE_MIN);
            v.z = fmaxf(v.z, SECURE_MIN); v.w = fmaxf(v.w, SECURE_MIN);
        }
        v.x *= inv; v.y *= inv; v.z *= inv; v.w *= inv;
        if (MODE != 1) ((float4*)(dst_f + base))[i] = v;
        if (MODE == 1) store_h4(dst_h + base, i, v, S_W);
        if (MODE == 2) store_h4(dst_h + base, i, v, S_H);
    }
}

// recon holds clip(h@Wn,1e-5). ratio_h = half(S_R * xn * max(rowsum,eps)/recon)
__global__ void ratio_kernel(const float* __restrict__ recon,
                             const float* __restrict__ xn,
                             __half* __restrict__ ratio_h, int cols) {
    const size_t base = (size_t)blockIdx.x * cols;
    const float4* r4 = (const float4*)(recon + base);
    const float4* x4 = (const float4*)(xn + base);
    const int n4 = cols >> 2;
    float sum = 0.0f;
    for (int i = threadIdx.x; i < n4; i += blockDim.x) {
        float4 v = r4[i];
        sum += v.x + v.y + v.z + v.w;
    }
    float s = block_reduce_sum(sum);
    s = fmaxf(s, EPS_NORM) * S_R;
    for (int i = threadIdx.x; i < n4; i += blockDim.x) {
        float4 v = r4[i];
        float4 x = x4[i];
        float4 o;
        o.x = x.x * s / v.x; o.y = x.y * s / v.y;
        o.z = x.z * s / v.z; o.w = x.w * s / v.w;
        half2* p = (half2*)(ratio_h + base + i * 4);
        p[0] = __floats2half2_rn(o.x, o.y);
        p[1] = __floats2half2_rn(o.z, o.w);
    }
}

__global__ void transpose_h_kernel(const __half* __restrict__ in,
                                   __half* __restrict__ out, int rows, int cols) {
    __shared__ __half tile[32][33];
    const int c  = blockIdx.x * 32 + threadIdx.x;
    const int r0 = blockIdx.y * 32;
#pragma unroll
    for (int i = threadIdx.y; i < 32; i += 8)
        tile[i][threadIdx.x] = in[(size_t)(r0 + i) * cols + c];
    __syncthreads();
    const int rO = r0 + threadIdx.x;
    const int c0 = blockIdx.x * 32;
#pragma unroll
    for (int i = threadIdx.y; i < 32; i += 8)
        out[(size_t)(c0 + i) * rows + rO] = tile[threadIdx.x][i];
}

__global__ void fill_kernel(float* __restrict__ a, __half* __restrict__ b,
                            float val, float val_h, int n) {
    const int i = blockIdx.x * blockDim.x + threadIdx.x;
    if (i < n) { a[i] = val; b[i] = __float2half_rn(val_h); }
}

// ---------------- host ----------------
extern "C" void kernel_launch(void* const* d_in, const int* in_sizes, int n_in,
                              void* d_out, int out_size) {
    const float* x = (const float*)d_in[0];  // (BATCH, F_IN)
    const float* W = (const float*)d_in[1];  // (F_OUT, F_IN)
    float* h = (float*)d_out;                // (BATCH, F_OUT)

    __half *Wn, *WnT, *rat, *ht;
    float *xn, *recon;
    cudaGetSymbolAddress((void**)&Wn,    g_Wn_h);
    cudaGetSymbolAddress((void**)&WnT,   g_WnT_h);
    cudaGetSymbolAddress((void**)&rat,   g_rat_h);
    cudaGetSymbolAddress((void**)&ht,    g_ht_h);
    cudaGetSymbolAddress((void**)&xn,    g_xn);
    cudaGetSymbolAddress((void**)&recon, g_recon);

    cudaFuncSetAttribute(gemm_f16<1>, cudaFuncAttributeMaxDynamicSharedMemorySize, SMEM_TOTAL);
    cudaFuncSetAttribute(gemm_f16<2>, cudaFuncAttributeMaxDynamicSharedMemorySize, SMEM_TOTAL);

    // prep
    rownorm_kernel<1><<<F_OUT, 256>>>(W, nullptr, Wn, F_IN);
    rownorm_kernel<0><<<BATCH, 256>>>(x, xn, nullptr, F_IN);
    transpose_h_kernel<<<dim3(F_IN / 32, F_OUT / 32), dim3(32, 8)>>>(Wn, WnT, F_OUT, F_IN);
    fill_kernel<<<(BATCH * F_OUT + 255) / 256, 256>>>(
        h, ht, 1.0f / (float)F_OUT, S_H / (float)F_OUT, BATCH * F_OUT);

    for (int it = 0; it < N_ITER; ++it) {
        // recon[B, F_IN] = ht @ Wn : A=ht (K=F_OUT), Brows=WnT [F_IN, F_OUT]
        gemm_f16<1><<<dim3(F_IN / BN, BATCH / BM), 256, SMEM_TOTAL>>>(
            ht, WnT, recon, F_OUT, F_IN, ESC1);
        ratio_kernel<<<BATCH, 256>>>(recon, xn, rat, F_IN);
        // h[B, F_OUT] = max(h * (ratio @ WnT), min) : A=rat (K=F_IN), Brows=Wn
        gemm_f16<2><<<dim3(F_OUT / BN, BATCH / BM), 256, SMEM_TOTAL>>>(
            rat, Wn, h, F_IN, F_OUT, ESC2);
        rownorm_kernel<2><<<BATCH, 256>>>(h, h, ht, F_OUT);
    }
}